// round 11
// baseline (speedup 1.0000x reference)
#include <cuda_runtime.h>
#include <math.h>

#define T_ 512
#define B_ 512
#define D_ 64
#define H_ 128
#define G_ 384
#define M_ (T_*B_)
#define YLEN 24
#define MTILES 2048          // M_/128
#define NCTA_X 37            // m-tile stride

// Scratch (device globals: allocation-free contract)
__device__ float g_gi[2u * M_ * G_];              // [dir][M][G]
__device__ float g_out0[(unsigned)M_ * 2 * H_];   // layer-0 output [M][256]
__device__ float g_hn[4 * B_ * H_];               // final hidden [cell][B][H]

typedef unsigned long long ull;

__device__ __forceinline__ float fsig(float x) { return 1.f / (1.f + __expf(-x)); }
__device__ __forceinline__ float ftanh(float x) { return 1.f - 2.f / (__expf(2.f * x) + 1.f); }

__device__ __forceinline__ unsigned cvt_tf32(unsigned x) {
    unsigned y;
    asm("cvt.rna.tf32.f32 %0, %1;" : "=r"(y) : "f"(__uint_as_float(x)));
    return y;
}

__device__ __forceinline__ void mma_tf32(float* c, const unsigned* a, const unsigned* b) {
    asm volatile(
        "mma.sync.aligned.m16n8k8.row.col.f32.tf32.tf32.f32 "
        "{%0,%1,%2,%3}, {%4,%5,%6,%7}, {%8,%9}, {%0,%1,%2,%3};"
        : "+f"(c[0]), "+f"(c[1]), "+f"(c[2]), "+f"(c[3])
        : "r"(a[0]), "r"(a[1]), "r"(a[2]), "r"(a[3]), "r"(b[0]), "r"(b[1]));
}

__device__ __forceinline__ unsigned smem_u32(const void* p) {
    return (unsigned)__cvta_generic_to_shared(p);
}

__device__ __forceinline__ void ldsm_x4(unsigned& r0, unsigned& r1,
                                        unsigned& r2, unsigned& r3, unsigned addr) {
    asm volatile("ldmatrix.sync.aligned.m8n8.x4.shared.b16 {%0,%1,%2,%3}, [%4];"
                 : "=r"(r0), "=r"(r1), "=r"(r2), "=r"(r3) : "r"(addr));
}

__device__ __forceinline__ void cp16(unsigned dst, const float* src) {
    asm volatile("cp.async.cg.shared.global [%0], [%1], 16;" :: "r"(dst), "l"(src));
}
__device__ __forceinline__ void cp_commit() {
    asm volatile("cp.async.commit_group;");
}
template<int N>
__device__ __forceinline__ void cp_wait() {
    asm volatile("cp.async.wait_group %0;" :: "n"(N));
}

// ---- packed f32x2 helpers (sm_103a) ----
__device__ __forceinline__ ull pack2(float a) {
    ull r;
    asm("mov.b64 %0, {%1, %1};" : "=l"(r) : "f"(a));
    return r;
}
__device__ __forceinline__ void fma2(ull& c, ull a, ull b) {
    asm("fma.rn.f32x2 %0, %1, %2, %0;" : "+l"(c) : "l"(a), "l"(b));
}
__device__ __forceinline__ float2 unpack2(ull v) {
    float2 f;
    asm("mov.b64 {%0, %1}, %2;" : "=f"(f.x), "=f"(f.y) : "l"(v));
    return f;
}

// ---------------------------------------------------------------------------
// Persistent TF32 gi GEMM with W cached in smem for CTA lifetime.
// Grid (37, 4): y = d*2 + nhalf. Each CTA: W slice [192][K] in smem (XOR-swz),
// loops m-tiles {bx, bx+37, ...}, A streamed via 2-stage cp.async ring.
// 256 threads = 8 warps (4M x 2N), warp tile 32x96.
// C[d][m][g] = A[m][:] . W[d][g][:] + bias[d][g]
// ---------------------------------------------------------------------------
#define A_STAGE_B 16384      // 128 rows x 32 floats x 4B

template<int K, int SRC_OUT0>
__global__ __launch_bounds__(256, 1) void gi_gemm_tf32(
    const float* __restrict__ Ain,
    const float* __restrict__ W,      // layer base [2][G][K]
    const float* __restrict__ bias)   // layer base [2][G]
{
    constexpr int KT = K / 32;
    constexpr int WROWB = K * 4;              // W smem row bytes
    constexpr int QPR = K / 4;                // 16B granules per W row

    const float* A = SRC_OUT0 ? g_out0 : Ain;
    extern __shared__ __align__(16) char smemc[];
    char* sW = smemc;                          // [192][WROWB]
    char* sA = smemc + 192 * WROWB;            // [2][A_STAGE_B]

    const int bx   = blockIdx.x;
    const int d    = blockIdx.y >> 1;
    const int nh   = blockIdx.y & 1;
    const int n0   = nh * 192;
    const int tid  = threadIdx.x;
    const int wid  = tid >> 5;
    const int lane = tid & 31;
    const int wm   = (wid & 3) * 32;
    const int wn   = (wid >> 2) * 96;
    const int gq   = lane >> 2;
    const int tg   = lane & 3;
    const int bRow = (lane & 7) | ((lane >> 4) << 3);

    const float* Wd = W + ((size_t)d * G_ + n0) * K;

    // ---- issue W fill (group 0) ----
    for (int id = tid; id < 192 * QPR; id += 256) {
        int n = id / QPR, q = id - n * QPR;
        int qs = (q & ~7) | ((q & 7) ^ (n & 7));
        cp16(smem_u32(sW + n * WROWB + (qs << 4)), Wd + (size_t)n * K + q * 4);
    }
    cp_commit();

    // number of m-tiles for this CTA
    const int nT = (MTILES - bx + NCTA_X - 1) / NCTA_X;
    const int nF = nT * KT;

    auto issueA = [&](int f) {
        const int mt = bx + (f / KT) * NCTA_X;
        const int k0 = (f % KT) * 32;
        char* dst = sA + (f & 1) * A_STAGE_B;
        const float* src = A + ((size_t)mt * 128) * K + k0;
#pragma unroll
        for (int it = 0; it < 4; it++) {
            int id = tid + it * 256;
            int r = id >> 3, q = id & 7;
            cp16(smem_u32(dst + r * 128 + ((q ^ (r & 7)) << 4)),
                 src + (size_t)r * K + q * 4);
        }
        cp_commit();
    };

    float acc[2][12][4];
#pragma unroll
    for (int mi = 0; mi < 2; mi++)
#pragma unroll
        for (int ni = 0; ni < 12; ni++)
#pragma unroll
            for (int j = 0; j < 4; j++) acc[mi][ni][j] = 0.f;

    issueA(0);

    for (int f = 0; f < nF; f++) {
        if (f + 1 < nF) { issueA(f + 1); cp_wait<1>(); }
        else            { cp_wait<0>(); }
        __syncthreads();

        const char* aBuf = sA + (f & 1) * A_STAGE_B;
        const int kt = f % KT;

#pragma unroll
        for (int kk = 0; kk < 4; kk++) {
            unsigned af[2][4], bf[12][2];
#pragma unroll
            for (int mi = 0; mi < 2; mi++) {
                int r = wm + mi * 16 + (lane & 15);
                int q = kk * 2 + (lane >> 4);
                unsigned ad = smem_u32(aBuf + r * 128 + ((q ^ (r & 7)) << 4));
                ldsm_x4(af[mi][0], af[mi][1], af[mi][2], af[mi][3], ad);
            }
#pragma unroll
            for (int nj = 0; nj < 6; nj++) {
                int n = wn + nj * 16 + bRow;
                int q = kt * 8 + kk * 2 + ((lane >> 3) & 1);
                int qs = (q & ~7) | ((q & 7) ^ (n & 7));
                unsigned ad = smem_u32(sW + n * WROWB + (qs << 4));
                ldsm_x4(bf[2*nj][0], bf[2*nj][1], bf[2*nj+1][0], bf[2*nj+1][1], ad);
            }
#pragma unroll
            for (int mi = 0; mi < 2; mi++)
#pragma unroll
                for (int j = 0; j < 4; j++) af[mi][j] = cvt_tf32(af[mi][j]);
#pragma unroll
            for (int ni = 0; ni < 12; ni++) {
                bf[ni][0] = cvt_tf32(bf[ni][0]);
                bf[ni][1] = cvt_tf32(bf[ni][1]);
            }
#pragma unroll
            for (int mi = 0; mi < 2; mi++)
#pragma unroll
                for (int ni = 0; ni < 12; ni++)
                    mma_tf32(acc[mi][ni], af[mi], bf[ni]);
        }

        if (kt == KT - 1) {
            // epilogue for tile f/KT
            const int mt = bx + (f / KT) * NCTA_X;
            float* C = g_gi + (size_t)d * M_ * G_;
            const float* bd = bias + (size_t)d * G_;
#pragma unroll
            for (int mi = 0; mi < 2; mi++) {
#pragma unroll
                for (int ni = 0; ni < 12; ni++) {
                    int gc = n0 + wn + ni * 8 + tg * 2;
                    float b0 = bd[gc], b1 = bd[gc + 1];
                    size_t r0 = (size_t)mt * 128 + wm + mi * 16 + gq;
                    *(float2*)(C + r0 * G_ + gc) =
                        make_float2(acc[mi][ni][0] + b0, acc[mi][ni][1] + b1);
                    *(float2*)(C + (r0 + 8) * G_ + gc) =
                        make_float2(acc[mi][ni][2] + b0, acc[mi][ni][3] + b1);
#pragma unroll
                    for (int j = 0; j < 4; j++) acc[mi][ni][j] = 0.f;
                }
            }
        }
        __syncthreads();
    }
}

// ---------------------------------------------------------------------------
// Persistent GRU scan, packed-f32x2 (unchanged from R7 passing version).
// ---------------------------------------------------------------------------
#define WPAD 388
__global__ __launch_bounds__(256, 1) void gru_scan(
    const float* __restrict__ Whh,
    const float* __restrict__ bhh,
    int writeOut, int hnBase)
{
    extern __shared__ __align__(16) float sm[];
    float* Wsh = sm;
    float* hs2 = sm + 128 * WPAD;

    const int d    = blockIdx.y;
    const int cb   = blockIdx.x * 8;
    const int tid  = threadIdx.x;
    const int t    = tid & 127;
    const int half = tid >> 7;

    const float* Wd = Whh + (size_t)d * G_ * H_;
    for (int i = tid; i < G_ * H_; i += 256) {
        int g = i >> 7, k = i & 127;
        Wsh[k * WPAD + g] = Wd[i];
    }
    for (int i = tid; i < 4 * 128 * 2; i += 256) hs2[i] = 0.f;

    float hreg[4];
#pragma unroll
    for (int j = 0; j < 4; j++) hreg[j] = 0.f;

    const float br = bhh[(size_t)d * G_ + t];
    const float bz = bhh[(size_t)d * G_ + 128 + t];
    const float bn = bhh[(size_t)d * G_ + 256 + t];
    __syncthreads();

    const float* giD = g_gi + (size_t)d * M_ * G_;

    for (int s = 0; s < T_; s++) {
        const int tt = d ? (T_ - 1 - s) : s;
        const float* gir = giD + ((size_t)tt * B_ + cb + half * 4) * G_;

        float gr[4], gz[4], gn[4];
#pragma unroll
        for (int j = 0; j < 4; j++) {
            gr[j] = __ldg(gir + (size_t)j * G_ + t);
            gz[j] = __ldg(gir + (size_t)j * G_ + 128 + t);
            gn[j] = __ldg(gir + (size_t)j * G_ + 256 + t);
        }

        ull ar2[2], az2[2], an2[2];
#pragma unroll
        for (int pp = 0; pp < 2; pp++) { ar2[pp] = 0ull; az2[pp] = 0ull; an2[pp] = 0ull; }

        const float* hbase0 = hs2 + (half * 2 + 0) * 256;
        const float* hbase1 = hs2 + (half * 2 + 1) * 256;

#pragma unroll 4
        for (int k4 = 0; k4 < H_; k4 += 4) {
            ulonglong2 u0a = *(const ulonglong2*)(hbase0 + k4 * 2);
            ulonglong2 u0b = *(const ulonglong2*)(hbase0 + k4 * 2 + 4);
            ulonglong2 u1a = *(const ulonglong2*)(hbase1 + k4 * 2);
            ulonglong2 u1b = *(const ulonglong2*)(hbase1 + k4 * 2 + 4);
            ull h0[4] = { u0a.x, u0a.y, u0b.x, u0b.y };
            ull h1[4] = { u1a.x, u1a.y, u1b.x, u1b.y };
#pragma unroll
            for (int kk = 0; kk < 4; kk++) {
                const float* wrow = &Wsh[(k4 + kk) * WPAD + t];
                ull wr2 = pack2(wrow[0]);
                ull wz2 = pack2(wrow[128]);
                ull wn2 = pack2(wrow[256]);
                fma2(ar2[0], h0[kk], wr2);
                fma2(az2[0], h0[kk], wz2);
                fma2(an2[0], h0[kk], wn2);
                fma2(ar2[1], h1[kk], wr2);
                fma2(az2[1], h1[kk], wz2);
                fma2(an2[1], h1[kk], wn2);
            }
        }

        float hnew[4];
#pragma unroll
        for (int pp = 0; pp < 2; pp++) {
            float2 arv = unpack2(ar2[pp]);
            float2 azv = unpack2(az2[pp]);
            float2 anv = unpack2(an2[pp]);
            float arr[2] = { arv.x, arv.y };
            float azz[2] = { azv.x, azv.y };
            float ann[2] = { anv.x, anv.y };
#pragma unroll
            for (int e = 0; e < 2; e++) {
                int j = pp * 2 + e;
                float rg = fsig(gr[j] + arr[e] + br);
                float zg = fsig(gz[j] + azz[e] + bz);
                float ng = ftanh(gn[j] + rg * (ann[e] + bn));
                hnew[j] = (1.f - zg) * ng + zg * hreg[j];
                hreg[j] = hnew[j];
            }
        }

        __syncthreads();
#pragma unroll
        for (int pp = 0; pp < 2; pp++) {
#pragma unroll
            for (int e = 0; e < 2; e++) {
                int j = pp * 2 + e;
                hs2[(half * 2 + pp) * 256 + t * 2 + e] = hnew[j];
                if (writeOut)
                    g_out0[((size_t)tt * B_ + cb + half * 4 + j) * (2 * H_) + d * H_ + t]
                        = hnew[j];
            }
        }
        __syncthreads();
    }

    float* hn = g_hn + (size_t)(hnBase + d) * B_ * H_;
#pragma unroll
    for (int j = 0; j < 4; j++)
        hn[(size_t)(cb + half * 4 + j) * H_ + t] = hreg[j];
}

// ---------------------------------------------------------------------------
// Decoder (unchanged from R7 passing version).
// ---------------------------------------------------------------------------
#define DR 4

__device__ __forceinline__ void dec_matvec(
    const float* __restrict__ W, int K,
    const float* __restrict__ vec, int ldv,
    float* __restrict__ outb,
    float bias, float* Ws2, int g, int tid)
{
    float acc[DR];
#pragma unroll
    for (int r = 0; r < DR; r++) acc[r] = 0.f;

    for (int kc = 0; kc < K; kc += 32) {
        __syncthreads();
        for (int id = tid; id < 384 * 8; id += 384) {
            int gp = id >> 3, kk4 = id & 7;
            float4 v = __ldg((const float4*)(W + (size_t)gp * K + kc + kk4 * 4));
            float* w = &Ws2[gp * 33 + kk4 * 4];
            w[0] = v.x; w[1] = v.y; w[2] = v.z; w[3] = v.w;
        }
        __syncthreads();
#pragma unroll 8
        for (int kk = 0; kk < 32; kk++) {
            float w = Ws2[g * 33 + kk];
#pragma unroll
            for (int r = 0; r < DR; r++)
                acc[r] = fmaf(vec[r * ldv + kc + kk], w, acc[r]);
        }
    }
#pragma unroll
    for (int r = 0; r < DR; r++) outb[r * G_ + g] = acc[r] + bias;
}

__global__ __launch_bounds__(384, 1) void decoder_kernel(
    const float* __restrict__ x,
    const float* __restrict__ dWih0,
    const float* __restrict__ dWih1,
    const float* __restrict__ dWhh,
    const float* __restrict__ dbih,
    const float* __restrict__ dbhh,
    const float* __restrict__ fcw,
    const float* __restrict__ fcb,
    float* __restrict__ out)
{
    extern __shared__ __align__(16) float dsm[];
    float* Ws2 = dsm;
    float* hsm = Ws2 + 384 * 33;
    float* lin = hsm + 4 * DR * H_;
    float* gis = lin + DR * 2 * H_;
    float* ghs = gis + DR * G_;
    float* fcs = ghs + DR * G_;
    float* xin = fcs + 2 * H_;

    const int tid = threadIdx.x;
    const int rb  = blockIdx.x * DR;
    const int g   = tid;

    for (int i = tid; i < 4 * DR * H_; i += 384) {
        int cell = i / (DR * H_);
        int rem  = i - cell * DR * H_;
        int r = rem >> 7, hc = rem & 127;
        hsm[cell * DR * H_ + r * H_ + hc] =
            g_hn[(size_t)cell * B_ * H_ + (size_t)(rb + r) * H_ + hc];
    }
    for (int i = tid; i < 2 * H_; i += 384) fcs[i] = fcw[i];
    if (tid < DR) xin[tid] = x[((size_t)(T_ - 1) * B_ + rb + tid) * D_];
    const float fb = fcb[0];
    __syncthreads();

    for (int step = 0; step < YLEN; step++) {
        for (int cell = 0; cell < 4; cell++) {
            const int l  = cell >> 1;
            const int dd = cell & 1;

            if (l == 0) {
                float wg = dWih0[(size_t)dd * G_ + g];
                float bg = dbih[(size_t)cell * G_ + g];
#pragma unroll
                for (int r = 0; r < DR; r++) gis[r * G_ + g] = xin[r] * wg + bg;
            } else {
                dec_matvec(dWih1 + (size_t)dd * G_ * (2 * H_), 2 * H_,
                           lin, 2 * H_, gis, dbih[(size_t)cell * G_ + g],
                           Ws2, g, tid);
            }
            dec_matvec(dWhh + (size_t)cell * G_ * H_, H_,
                       hsm + cell * DR * H_, H_, ghs, dbhh[(size_t)cell * G_ + g],
                       Ws2, g, tid);
            __syncthreads();

            for (int i = tid; i < DR * H_; i += 384) {
                int r = i >> 7, hc = i & 127;
                float rg = fsig(gis[r * G_ + hc]       + ghs[r * G_ + hc]);
                float zg = fsig(gis[r * G_ + 128 + hc] + ghs[r * G_ + 128 + hc]);
                float ng = ftanh(gis[r * G_ + 256 + hc] + rg * ghs[r * G_ + 256 + hc]);
                float ho = hsm[cell * DR * H_ + r * H_ + hc];
                float hv = (1.f - zg) * ng + zg * ho;
                hsm[cell * DR * H_ + r * H_ + hc] = hv;
                if (l == 0) lin[r * 2 * H_ + dd * H_ + hc] = hv;
            }
            __syncthreads();
        }

        if (tid < 32 * DR) {
            int r = tid >> 5, ln = tid & 31;
            float p = 0.f;
            for (int i = ln; i < H_; i += 32)
                p += hsm[2 * DR * H_ + r * H_ + i] * fcs[i]
                   + hsm[3 * DR * H_ + r * H_ + i] * fcs[H_ + i];
#pragma unroll
            for (int off = 16; off > 0; off >>= 1)
                p += __shfl_xor_sync(0xffffffffu, p, off);
            if (ln == 0) {
                float pred = p + fb;
                out[(size_t)step * B_ + rb + r] = pred;
                xin[r] = pred;
            }
        }
        __syncthreads();
    }
}

// ---------------------------------------------------------------------------
extern "C" void kernel_launch(void* const* d_in, const int* in_sizes, int n_in,
                              void* d_out, int out_size)
{
    const float* x        = (const float*)d_in[0];
    const float* enc_Wih0 = (const float*)d_in[1];
    const float* enc_Wih1 = (const float*)d_in[2];
    const float* enc_Whh  = (const float*)d_in[3];
    const float* enc_bih  = (const float*)d_in[4];
    const float* enc_bhh  = (const float*)d_in[5];
    const float* dec_Wih0 = (const float*)d_in[6];
    const float* dec_Wih1 = (const float*)d_in[7];
    const float* dec_Whh  = (const float*)d_in[8];
    const float* dec_bih  = (const float*)d_in[9];
    const float* dec_bhh  = (const float*)d_in[10];
    const float* fc_w     = (const float*)d_in[11];
    const float* fc_b     = (const float*)d_in[12];
    float* out = (float*)d_out;

    const int gemm0Smem = 192 * (D_ * 4) + 2 * A_STAGE_B;       // 49152+32768
    const int gemm1Smem = 192 * (2 * H_ * 4) + 2 * A_STAGE_B;   // 196608+32768=229376
    const int scanSmem  = (128 * WPAD + 4 * 128 * 2) * 4;
    const int decSmem   = (384 * 33 + 4 * DR * H_ + DR * 2 * H_ +
                           2 * DR * G_ + 2 * H_ + DR + 4) * 4;

    cudaFuncSetAttribute(gi_gemm_tf32<D_, 0>,
                         cudaFuncAttributeMaxDynamicSharedMemorySize, gemm0Smem);
    cudaFuncSetAttribute(gi_gemm_tf32<2 * H_, 1>,
                         cudaFuncAttributeMaxDynamicSharedMemorySize, gemm1Smem);
    cudaFuncSetAttribute(gru_scan, cudaFuncAttributeMaxDynamicSharedMemorySize, scanSmem);
    cudaFuncSetAttribute(decoder_kernel, cudaFuncAttributeMaxDynamicSharedMemorySize, decSmem);

    // encoder layer 0
    gi_gemm_tf32<D_, 0><<<dim3(NCTA_X, 4), 256, gemm0Smem>>>(x, enc_Wih0, enc_bih);
    gru_scan<<<dim3(B_ / 8, 2), 256, scanSmem>>>(enc_Whh, enc_bhh, 1, 0);

    // encoder layer 1
    gi_gemm_tf32<2 * H_, 1><<<dim3(NCTA_X, 4), 256, gemm1Smem>>>(x, enc_Wih1, enc_bih + 2 * G_);
    gru_scan<<<dim3(B_ / 8, 2), 256, scanSmem>>>(enc_Whh + 2 * G_ * H_,
                                                 enc_bhh + 2 * G_, 0, 2);

    // decoder
    decoder_kernel<<<B_ / DR, 384, decSmem>>>(x, dec_Wih0, dec_Wih1, dec_Whh,
                                              dec_bih, dec_bhh, fc_w, fc_b, out);
}

// round 15
// speedup vs baseline: 1.0369x; 1.0369x over previous
#include <cuda_runtime.h>
#include <math.h>

#define T_ 512
#define B_ 512
#define D_ 64
#define H_ 128
#define G_ 384
#define M_ (T_*B_)
#define YLEN 24
#define MTILES 2048
#define NCTA_X 37

__device__ float g_gi[2u * M_ * G_];
__device__ float g_out0[(unsigned)M_ * 2 * H_];
__device__ float g_hn[4 * B_ * H_];
__device__ float g_dh[4 * B_ * H_];
__device__ float g_lin[B_ * 2 * H_];
__device__ float g_xin[B_];
__device__ float g_wtih1[2 * 256 * 384];
__device__ float g_wtwhh[4 * 128 * 384];

typedef unsigned long long ull;

__device__ __forceinline__ float fsig(float x) { return 1.f / (1.f + __expf(-x)); }
__device__ __forceinline__ float ftanh(float x) { return 1.f - 2.f / (__expf(2.f * x) + 1.f); }
__device__ __forceinline__ unsigned cvt_tf32(unsigned x) {
    unsigned y;
    asm("cvt.rna.tf32.f32 %0, %1;" : "=r"(y) : "f"(__uint_as_float(x)));
    return y;
}
__device__ __forceinline__ void mma_tf32(float* c, const unsigned* a, const unsigned* b) {
    asm volatile(
        "mma.sync.aligned.m16n8k8.row.col.f32.tf32.tf32.f32 "
        "{%0,%1,%2,%3}, {%4,%5,%6,%7}, {%8,%9}, {%0,%1,%2,%3};"
        : "+f"(c[0]), "+f"(c[1]), "+f"(c[2]), "+f"(c[3])
        : "r"(a[0]), "r"(a[1]), "r"(a[2]), "r"(a[3]), "r"(b[0]), "r"(b[1]));
}
__device__ __forceinline__ unsigned smem_u32(const void* p) {
    return (unsigned)__cvta_generic_to_shared(p);
}
__device__ __forceinline__ void ldsm_x4(unsigned& r0, unsigned& r1,
                                        unsigned& r2, unsigned& r3, unsigned addr) {
    asm volatile("ldmatrix.sync.aligned.m8n8.x4.shared.b16 {%0,%1,%2,%3}, [%4];"
                 : "=r"(r0), "=r"(r1), "=r"(r2), "=r"(r3) : "r"(addr));
}
__device__ __forceinline__ void cp16(unsigned dst, const float* src) {
    asm volatile("cp.async.cg.shared.global [%0], [%1], 16;" :: "r"(dst), "l"(src));
}
__device__ __forceinline__ void cp_commit() { asm volatile("cp.async.commit_group;"); }
template<int N> __device__ __forceinline__ void cp_wait() {
    asm volatile("cp.async.wait_group %0;" :: "n"(N));
}
__device__ __forceinline__ ull pack2(float a) {
    ull r; asm("mov.b64 %0, {%1, %1};" : "=l"(r) : "f"(a)); return r;
}
__device__ __forceinline__ void fma2(ull& c, ull a, ull b) {
    asm("fma.rn.f32x2 %0, %1, %2, %0;" : "+l"(c) : "l"(a), "l"(b));
}
__device__ __forceinline__ float2 unpack2(ull v) {
    float2 f; asm("mov.b64 {%0, %1}, %2;" : "=f"(f.x), "=f"(f.y) : "l"(v)); return f;
}

// ---------------------------------------------------------------------------
// Persistent TF32 gi GEMM (R9-proven, verbatim).
// ---------------------------------------------------------------------------
#define A_STAGE_B 16384

template<int K, int SRC_OUT0>
__global__ __launch_bounds__(256, 1) void gi_gemm_tf32(
    const float* __restrict__ Ain,
    const float* __restrict__ W,
    const float* __restrict__ bias)
{
    constexpr int KT = K / 32;
    constexpr int WROWB = K * 4;
    constexpr int QPR = K / 4;

    const float* A = SRC_OUT0 ? g_out0 : Ain;
    extern __shared__ __align__(16) char smemc[];
    char* sW = smemc;
    char* sA = smemc + 192 * WROWB;

    const int bx   = blockIdx.x;
    const int d    = blockIdx.y >> 1;
    const int nh   = blockIdx.y & 1;
    const int n0   = nh * 192;
    const int tid  = threadIdx.x;
    const int wid  = tid >> 5;
    const int lane = tid & 31;
    const int wm   = (wid & 3) * 32;
    const int wn   = (wid >> 2) * 96;
    const int gq   = lane >> 2;
    const int tg   = lane & 3;
    const int bRow = (lane & 7) | ((lane >> 4) << 3);

    const float* Wd = W + ((size_t)d * G_ + n0) * K;

    for (int id = tid; id < 192 * QPR; id += 256) {
        int n = id / QPR, q = id - n * QPR;
        int qs = (q & ~7) | ((q & 7) ^ (n & 7));
        cp16(smem_u32(sW + n * WROWB + (qs << 4)), Wd + (size_t)n * K + q * 4);
    }
    cp_commit();

    const int nT = (MTILES - bx + NCTA_X - 1) / NCTA_X;
    const int nF = nT * KT;

    auto issueA = [&](int f) {
        const int mt = bx + (f / KT) * NCTA_X;
        const int k0 = (f % KT) * 32;
        char* dst = sA + (f & 1) * A_STAGE_B;
        const float* src = A + ((size_t)mt * 128) * K + k0;
#pragma unroll
        for (int it = 0; it < 4; it++) {
            int id = tid + it * 256;
            int r = id >> 3, q = id & 7;
            cp16(smem_u32(dst + r * 128 + ((q ^ (r & 7)) << 4)),
                 src + (size_t)r * K + q * 4);
        }
        cp_commit();
    };

    float acc[2][12][4];
#pragma unroll
    for (int mi = 0; mi < 2; mi++)
#pragma unroll
        for (int ni = 0; ni < 12; ni++)
#pragma unroll
            for (int j = 0; j < 4; j++) acc[mi][ni][j] = 0.f;

    issueA(0);

    for (int f = 0; f < nF; f++) {
        if (f + 1 < nF) { issueA(f + 1); cp_wait<1>(); }
        else            { cp_wait<0>(); }
        __syncthreads();

        const char* aBuf = sA + (f & 1) * A_STAGE_B;
        const int kt = f % KT;

#pragma unroll
        for (int kk = 0; kk < 4; kk++) {
            unsigned af[2][4], bf[12][2];
#pragma unroll
            for (int mi = 0; mi < 2; mi++) {
                int r = wm + mi * 16 + (lane & 15);
                int q = kk * 2 + (lane >> 4);
                unsigned ad = smem_u32(aBuf + r * 128 + ((q ^ (r & 7)) << 4));
                ldsm_x4(af[mi][0], af[mi][1], af[mi][2], af[mi][3], ad);
            }
#pragma unroll
            for (int nj = 0; nj < 6; nj++) {
                int n = wn + nj * 16 + bRow;
                int q = kt * 8 + kk * 2 + ((lane >> 3) & 1);
                int qs = (q & ~7) | ((q & 7) ^ (n & 7));
                unsigned ad = smem_u32(sW + n * WROWB + (qs << 4));
                ldsm_x4(bf[2*nj][0], bf[2*nj][1], bf[2*nj+1][0], bf[2*nj+1][1], ad);
            }
#pragma unroll
            for (int mi = 0; mi < 2; mi++)
#pragma unroll
                for (int j = 0; j < 4; j++) af[mi][j] = cvt_tf32(af[mi][j]);
#pragma unroll
            for (int ni = 0; ni < 12; ni++) {
                bf[ni][0] = cvt_tf32(bf[ni][0]);
                bf[ni][1] = cvt_tf32(bf[ni][1]);
            }
#pragma unroll
            for (int mi = 0; mi < 2; mi++)
#pragma unroll
                for (int ni = 0; ni < 12; ni++)
                    mma_tf32(acc[mi][ni], af[mi], bf[ni]);
        }

        if (kt == KT - 1) {
            const int mt = bx + (f / KT) * NCTA_X;
            float* C = g_gi + (size_t)d * M_ * G_;
            const float* bd = bias + (size_t)d * G_;
#pragma unroll
            for (int mi = 0; mi < 2; mi++) {
#pragma unroll
                for (int ni = 0; ni < 12; ni++) {
                    int gc = n0 + wn + ni * 8 + tg * 2;
                    float b0 = bd[gc], b1 = bd[gc + 1];
                    size_t r0 = (size_t)mt * 128 + wm + mi * 16 + gq;
                    *(float2*)(C + r0 * G_ + gc) =
                        make_float2(acc[mi][ni][0] + b0, acc[mi][ni][1] + b1);
                    *(float2*)(C + (r0 + 8) * G_ + gc) =
                        make_float2(acc[mi][ni][2] + b0, acc[mi][ni][3] + b1);
#pragma unroll
                    for (int j = 0; j < 4; j++) acc[mi][ni][j] = 0.f;
                }
            }
        }
        __syncthreads();
    }
}

// ---------------------------------------------------------------------------
// Persistent GRU scan, packed-f32x2 (R9-proven, verbatim).
// ---------------------------------------------------------------------------
#define WPAD 388
__global__ __launch_bounds__(256, 1) void gru_scan(
    const float* __restrict__ Whh, const float* __restrict__ bhh,
    int writeOut, int hnBase)
{
    extern __shared__ __align__(16) float sm[];
    float* Wsh = sm;
    float* hs2 = sm + 128 * WPAD;
    const int d = blockIdx.y, cb = blockIdx.x * 8;
    const int tid = threadIdx.x, t = tid & 127, half = tid >> 7;

    const float* Wd = Whh + (size_t)d * G_ * H_;
    for (int i = tid; i < G_ * H_; i += 256) {
        int g = i >> 7, k = i & 127;
        Wsh[k * WPAD + g] = Wd[i];
    }
    for (int i = tid; i < 4 * 128 * 2; i += 256) hs2[i] = 0.f;
    float hreg[4];
#pragma unroll
    for (int j = 0; j < 4; j++) hreg[j] = 0.f;
    const float br = bhh[(size_t)d * G_ + t];
    const float bz = bhh[(size_t)d * G_ + 128 + t];
    const float bn = bhh[(size_t)d * G_ + 256 + t];
    __syncthreads();

    const float* giD = g_gi + (size_t)d * M_ * G_;
    for (int s = 0; s < T_; s++) {
        const int tt = d ? (T_ - 1 - s) : s;
        const float* gir = giD + ((size_t)tt * B_ + cb + half * 4) * G_;
        float gr[4], gz[4], gn[4];
#pragma unroll
        for (int j = 0; j < 4; j++) {
            gr[j] = __ldg(gir + (size_t)j * G_ + t);
            gz[j] = __ldg(gir + (size_t)j * G_ + 128 + t);
            gn[j] = __ldg(gir + (size_t)j * G_ + 256 + t);
        }
        ull ar2[2], az2[2], an2[2];
#pragma unroll
        for (int pp = 0; pp < 2; pp++) { ar2[pp] = 0; az2[pp] = 0; an2[pp] = 0; }
        const float* hb0 = hs2 + (half * 2 + 0) * 256;
        const float* hb1 = hs2 + (half * 2 + 1) * 256;
#pragma unroll 4
        for (int k4 = 0; k4 < H_; k4 += 4) {
            ulonglong2 u0a = *(const ulonglong2*)(hb0 + k4 * 2);
            ulonglong2 u0b = *(const ulonglong2*)(hb0 + k4 * 2 + 4);
            ulonglong2 u1a = *(const ulonglong2*)(hb1 + k4 * 2);
            ulonglong2 u1b = *(const ulonglong2*)(hb1 + k4 * 2 + 4);
            ull h0[4] = { u0a.x, u0a.y, u0b.x, u0b.y };
            ull h1[4] = { u1a.x, u1a.y, u1b.x, u1b.y };
#pragma unroll
            for (int kk = 0; kk < 4; kk++) {
                const float* wrow = &Wsh[(k4 + kk) * WPAD + t];
                ull wr2 = pack2(wrow[0]);
                ull wz2 = pack2(wrow[128]);
                ull wn2 = pack2(wrow[256]);
                fma2(ar2[0], h0[kk], wr2); fma2(az2[0], h0[kk], wz2); fma2(an2[0], h0[kk], wn2);
                fma2(ar2[1], h1[kk], wr2); fma2(az2[1], h1[kk], wz2); fma2(an2[1], h1[kk], wn2);
            }
        }
        float hnew[4];
#pragma unroll
        for (int pp = 0; pp < 2; pp++) {
            float2 arv = unpack2(ar2[pp]), azv = unpack2(az2[pp]), anv = unpack2(an2[pp]);
            float arr[2] = { arv.x, arv.y }, azz[2] = { azv.x, azv.y }, ann[2] = { anv.x, anv.y };
#pragma unroll
            for (int e = 0; e < 2; e++) {
                int j = pp * 2 + e;
                float rg = fsig(gr[j] + arr[e] + br);
                float zg = fsig(gz[j] + azz[e] + bz);
                float ng = ftanh(gn[j] + rg * (ann[e] + bn));
                hnew[j] = (1.f - zg) * ng + zg * hreg[j];
                hreg[j] = hnew[j];
            }
        }
        __syncthreads();
#pragma unroll
        for (int pp = 0; pp < 2; pp++)
#pragma unroll
            for (int e = 0; e < 2; e++) {
                int j = pp * 2 + e;
                hs2[(half * 2 + pp) * 256 + t * 2 + e] = hnew[j];
                if (writeOut)
                    g_out0[((size_t)tt * B_ + cb + half * 4 + j) * (2 * H_) + d * H_ + t] = hnew[j];
            }
        __syncthreads();
    }
    float* hn = g_hn + (size_t)(hnBase + d) * B_ * H_;
#pragma unroll
    for (int j = 0; j < 4; j++)
        hn[(size_t)(cb + half * 4 + j) * H_ + t] = hreg[j];
}

// ---------------------------------------------------------------------------
// One-time decoder weight transpose to k-major [k4][384][4] layout.
// ---------------------------------------------------------------------------
__global__ __launch_bounds__(256) void t_wt(const float* __restrict__ wih1,
                                            const float* __restrict__ whh) {
    int i = blockIdx.x * 256 + threadIdx.x;   // grid 768 -> 196608 = both sizes
    {
        int d = i / (384 * 256), rem = i % (384 * 256);
        int g = rem / 256, k = rem % 256;
        g_wtih1[((size_t)(d * 64 + (k >> 2)) * 384 + g) * 4 + (k & 3)] = wih1[i];
    }
    {
        int c = i / (384 * 128), rem = i % (384 * 128);
        int g = rem / 128, k = rem % 128;
        g_wtwhh[((size_t)(c * 32 + (k >> 2)) * 384 + g) * 4 + (k & 3)] = whh[i];
    }
}

// ---------------------------------------------------------------------------
// Decoder per-step kernels: staging-free matvecs (coalesced LDG.128 weights).
// ---------------------------------------------------------------------------
__global__ __launch_bounds__(384) void dec_l0(
    const float* __restrict__ x, const float* __restrict__ dWih0,
    const float* __restrict__ dbih, const float* __restrict__ dbhh, int s)
{
    __shared__ float sh_h[8][128];
    __shared__ float sh_g[8][384];
    const int rb = blockIdx.x * 8;
    const int dd = blockIdx.y;
    const int cell = dd;
    const int tid = threadIdx.x;

    const float* hsrc = (s == 0 ? g_hn : g_dh) + (size_t)cell * B_ * H_;
    for (int i = tid; i < 8 * 128; i += 384)
        sh_h[i >> 7][i & 127] = hsrc[(size_t)(rb + (i >> 7)) * H_ + (i & 127)];
    __syncthreads();

    {
        const int g = tid;
        float acc[8] = {0.f,0.f,0.f,0.f,0.f,0.f,0.f,0.f};
        const float* wt = g_wtwhh + (size_t)cell * 32 * 384 * 4;
        for (int k4 = 0; k4 < 32; k4++) {
            float4 w = *(const float4*)(wt + ((size_t)k4 * 384 + g) * 4);
#pragma unroll
            for (int r = 0; r < 8; r++) {
                float4 hv = *(const float4*)&sh_h[r][k4 * 4];
                acc[r] = fmaf(w.x, hv.x, fmaf(w.y, hv.y, fmaf(w.z, hv.z, fmaf(w.w, hv.w, acc[r]))));
            }
        }
        float bb = dbhh[cell * G_ + g];
#pragma unroll
        for (int r = 0; r < 8; r++) sh_g[r][g] = acc[r] + bb;
    }
    __syncthreads();

    for (int i = tid; i < 8 * 128; i += 384) {
        int r = i >> 7, c = i & 127, row = rb + r;
        float xv = (s == 0) ? x[((size_t)(T_ - 1) * B_ + row) * D_] : g_xin[row];
        float gir = xv * dWih0[dd * G_ + c]       + dbih[cell * G_ + c];
        float giz = xv * dWih0[dd * G_ + 128 + c] + dbih[cell * G_ + 128 + c];
        float gin = xv * dWih0[dd * G_ + 256 + c] + dbih[cell * G_ + 256 + c];
        float rg = fsig(gir + sh_g[r][c]);
        float zg = fsig(giz + sh_g[r][c + 128]);
        float ng = ftanh(gin + rg * sh_g[r][c + 256]);
        float hv = (1.f - zg) * ng + zg * sh_h[r][c];
        g_dh[(size_t)cell * B_ * H_ + (size_t)row * H_ + c] = hv;
        g_lin[(size_t)row * 256 + dd * 128 + c] = hv;
    }
}

__global__ __launch_bounds__(384) void dec_l1(
    const float* __restrict__ dbih, const float* __restrict__ dbhh, int s)
{
    __shared__ float sh_lin[8][256];
    __shared__ float sh_h[8][128];
    __shared__ float sh_gi[8][384];
    __shared__ float sh_gh[8][384];
    const int rb = blockIdx.x * 8;
    const int dd = blockIdx.y;
    const int cell = 2 + dd;
    const int tid = threadIdx.x;
    const int g = tid;

    const float* hsrc = (s == 0 ? g_hn : g_dh) + (size_t)cell * B_ * H_;
    for (int i = tid; i < 8 * 128; i += 384)
        sh_h[i >> 7][i & 127] = hsrc[(size_t)(rb + (i >> 7)) * H_ + (i & 127)];
    for (int i = tid; i < 8 * 256; i += 384)
        sh_lin[i >> 8][i & 255] = g_lin[(size_t)(rb + (i >> 8)) * 256 + (i & 255)];
    __syncthreads();

    {
        float acc[8] = {0.f,0.f,0.f,0.f,0.f,0.f,0.f,0.f};
        const float* wt = g_wtih1 + (size_t)dd * 64 * 384 * 4;
        for (int k4 = 0; k4 < 64; k4++) {
            float4 w = *(const float4*)(wt + ((size_t)k4 * 384 + g) * 4);
#pragma unroll
            for (int r = 0; r < 8; r++) {
                float4 v = *(const float4*)&sh_lin[r][k4 * 4];
                acc[r] = fmaf(w.x, v.x, fmaf(w.y, v.y, fmaf(w.z, v.z, fmaf(w.w, v.w, acc[r]))));
            }
        }
        float bb = dbih[cell * G_ + g];
#pragma unroll
        for (int r = 0; r < 8; r++) sh_gi[r][g] = acc[r] + bb;
    }
    {
        float acc[8] = {0.f,0.f,0.f,0.f,0.f,0.f,0.f,0.f};
        const float* wt = g_wtwhh + (size_t)cell * 32 * 384 * 4;
        for (int k4 = 0; k4 < 32; k4++) {
            float4 w = *(const float4*)(wt + ((size_t)k4 * 384 + g) * 4);
#pragma unroll
            for (int r = 0; r < 8; r++) {
                float4 hv = *(const float4*)&sh_h[r][k4 * 4];
                acc[r] = fmaf(w.x, hv.x, fmaf(w.y, hv.y, fmaf(w.z, hv.z, fmaf(w.w, hv.w, acc[r]))));
            }
        }
        float bb = dbhh[cell * G_ + g];
#pragma unroll
        for (int r = 0; r < 8; r++) sh_gh[r][g] = acc[r] + bb;
    }
    __syncthreads();

    for (int i = tid; i < 8 * 128; i += 384) {
        int r = i >> 7, c = i & 127, row = rb + r;
        float rg = fsig(sh_gi[r][c] + sh_gh[r][c]);
        float zg = fsig(sh_gi[r][c + 128] + sh_gh[r][c + 128]);
        float ng = ftanh(sh_gi[r][c + 256] + rg * sh_gh[r][c + 256]);
        float hv = (1.f - zg) * ng + zg * sh_h[r][c];
        g_dh[(size_t)cell * B_ * H_ + (size_t)row * H_ + c] = hv;
    }
}

__global__ __launch_bounds__(128) void dec_fc(
    const float* __restrict__ fcw, const float* __restrict__ fcb,
    float* __restrict__ out, int s)
{
    const int w = threadIdx.x >> 5, ln = threadIdx.x & 31;
    const float fb = fcb[0];
    for (int rr = 0; rr < 8; rr++) {
        int row = (blockIdx.x * 4 + w) * 8 + rr;
        float p = 0.f;
#pragma unroll
        for (int j = 0; j < 4; j++) {
            int c = ln + j * 32;
            p += g_dh[(size_t)2 * B_ * H_ + (size_t)row * H_ + c] * fcw[c]
               + g_dh[(size_t)3 * B_ * H_ + (size_t)row * H_ + c] * fcw[128 + c];
        }
#pragma unroll
        for (int off = 16; off > 0; off >>= 1)
            p += __shfl_xor_sync(0xffffffffu, p, off);
        if (ln == 0) {
            float pr = p + fb;
            out[(size_t)s * B_ + row] = pr;
            g_xin[row] = pr;
        }
    }
}

// ---------------------------------------------------------------------------
extern "C" void kernel_launch(void* const* d_in, const int* in_sizes, int n_in,
                              void* d_out, int out_size)
{
    const float* x        = (const float*)d_in[0];
    const float* enc_Wih0 = (const float*)d_in[1];
    const float* enc_Wih1 = (const float*)d_in[2];
    const float* enc_Whh  = (const float*)d_in[3];
    const float* enc_bih  = (const float*)d_in[4];
    const float* enc_bhh  = (const float*)d_in[5];
    const float* dec_Wih0 = (const float*)d_in[6];
    const float* dec_Wih1 = (const float*)d_in[7];
    const float* dec_Whh  = (const float*)d_in[8];
    const float* dec_bih  = (const float*)d_in[9];
    const float* dec_bhh  = (const float*)d_in[10];
    const float* fc_w     = (const float*)d_in[11];
    const float* fc_b     = (const float*)d_in[12];
    float* out = (float*)d_out;

    const int gemm0Smem = 192 * (D_ * 4) + 2 * A_STAGE_B;
    const int gemm1Smem = 192 * (2 * H_ * 4) + 2 * A_STAGE_B;
    const int scanSmem  = (128 * WPAD + 4 * 128 * 2) * 4;

    cudaFuncSetAttribute(gi_gemm_tf32<D_, 0>,
                         cudaFuncAttributeMaxDynamicSharedMemorySize, gemm0Smem);
    cudaFuncSetAttribute(gi_gemm_tf32<2 * H_, 1>,
                         cudaFuncAttributeMaxDynamicSharedMemorySize, gemm1Smem);
    cudaFuncSetAttribute(gru_scan, cudaFuncAttributeMaxDynamicSharedMemorySize, scanSmem);

    t_wt<<<768, 256>>>(dec_Wih1, dec_Whh);

    gi_gemm_tf32<D_, 0><<<dim3(NCTA_X, 4), 256, gemm0Smem>>>(x, enc_Wih0, enc_bih);
    gru_scan<<<dim3(B_ / 8, 2), 256, scanSmem>>>(enc_Whh, enc_bhh, 1, 0);
    gi_gemm_tf32<2 * H_, 1><<<dim3(NCTA_X, 4), 256, gemm1Smem>>>(x, enc_Wih1, enc_bih + 2 * G_);
    gru_scan<<<dim3(B_ / 8, 2), 256, scanSmem>>>(enc_Whh + 2 * G_ * H_, enc_bhh + 2 * G_, 0, 2);

    for (int s = 0; s < YLEN; s++) {
        dec_l0<<<dim3(64, 2), 384>>>(x, dec_Wih0, dec_bih, dec_bhh, s);
        dec_l1<<<dim3(64, 2), 384>>>(dec_bih, dec_bhh, s);
        dec_fc<<<16, 128>>>(fc_w, fc_b, out, s);
    }
}